// round 10
// baseline (speedup 1.0000x reference)
#include <cuda_runtime.h>
#include <math.h>

#define Bq 4
#define Lq 2048
#define Hq 8
#define Dq 64
#define NSLOT 12                 // self + offsets 2^0 .. 2^10
#define SLAB4 (Hq * Dq / 4)      // 128 x 16B chunks per (b,l) slab

// One warp per (b, l, head-pair); lane ln owns 16B chunk ln of the 512B
// contiguous head-pair slab (lanes 0-15 even head, 16-31 odd head).
template <bool FULL>
__device__ __forceinline__ void run_query(
    const float4* __restrict__ Q4, const float4* __restrict__ K4,
    const float4* __restrict__ V4, float4* __restrict__ O4,
    int base, int l, int hl)     // hl = lane & 15 (index within half)
{
    const float4 q = Q4[base];

    // ---- phase 1: 12 front-batched K loads, per-lane partial dots ----
    float v[16];
#pragma unroll
    for (int t = 0; t < NSLOT; t++) {
        const int off = (t == 0) ? 0 : (1 << (t - 1));
        const bool ok = FULL || (off <= l);
        const int kb = base - (ok ? off * SLAB4 : 0);  // imm offset in FULL path
        const float4 k = K4[kb];
        v[t] = q.x*k.x + q.y*k.y + q.z*k.z + q.w*k.w;
    }
#pragma unroll
    for (int t = NSLOT; t < 16; t++) v[t] = 0.0f;

    // ---- multi-value butterfly: 15 shfls reduce ALL 16 slots; after this,
    //      lane hl (in each 16-lane half) holds the full dot of slot hl ----
#pragma unroll
    for (int m = 8; m >= 1; m >>= 1) {
#pragma unroll
        for (int j = 0; j < m; j++) {
            const float send = (hl & m) ? v[j] : v[j + m];
            const float other = __shfl_xor_sync(0xffffffffu, send, m);
            v[j] = ((hl & m) ? v[j + m] : v[j]) + other;
        }
    }
    const float score = v[0] * 0.125f;   // 1/sqrt(64), folded post-reduce

    // per-lane validity of slot hl
    bool okl;
    if (FULL) okl = (hl < NSLOT);
    else      okl = (hl == 0) || ((hl < NSLOT) && ((1 << (hl - 1)) <= l));

    // one exp instruction covers all 12 slots (scores ~N(0,1): no overflow)
    const float e = okl ? __expf(score) : 0.0f;

    // 16-lane butterfly sum of e -> denominator in every lane
    float sum = e;
    sum += __shfl_xor_sync(0xffffffffu, sum, 1);
    sum += __shfl_xor_sync(0xffffffffu, sum, 2);
    sum += __shfl_xor_sync(0xffffffffu, sum, 4);
    sum += __shfl_xor_sync(0xffffffffu, sum, 8);
    const float inv = 1.0f / sum;

    // ---- phase 2: V gathers (addresses independent of exp/sum chain; ptxas
    //      hoists loads into the butterfly/exp shadow as registers free up),
    //      width-16 prob broadcast + weighted accumulate ----
    float4 acc = {0.f, 0.f, 0.f, 0.f};
#pragma unroll
    for (int t = 0; t < NSLOT; t++) {
        const int off = (t == 0) ? 0 : (1 << (t - 1));
        const bool ok = FULL || (off <= l);
        const int vb = base - (ok ? off * SLAB4 : 0);
        const float4 vv = V4[vb];
        const float p = __shfl_sync(0xffffffffu, e, t, 16);  // 0 if slot invalid
        acc.x += p * vv.x;
        acc.y += p * vv.y;
        acc.z += p * vv.z;
        acc.w += p * vv.w;
    }
    acc.x *= inv; acc.y *= inv; acc.z *= inv; acc.w *= inv;
    O4[base] = acc;
}

__global__ __launch_bounds__(256, 6) void logsparse_attn_kernel(
    const float4* __restrict__ Q4,
    const float4* __restrict__ K4,
    const float4* __restrict__ V4,
    float4* __restrict__ O4)
{
    const int wid  = (blockIdx.x * blockDim.x + threadIdx.x) >> 5;
    const int lane = threadIdx.x & 31;
    const int g = wid & (Hq / 2 - 1);            // head-pair 0..3
    const int s = wid >> 2;                      // b*L + l
    const int l = s & (Lq - 1);

    const int base = s * SLAB4 + g * 32 + lane;  // 16B-chunk index
    const int hl = lane & 15;

    if (l >= 1024) {
        run_query<true>(Q4, K4, V4, O4, base, l, hl);
    } else {
        run_query<false>(Q4, K4, V4, O4, base, l, hl);
    }
}

extern "C" void kernel_launch(void* const* d_in, const int* in_sizes, int n_in,
                              void* d_out, int out_size)
{
    const float4* Q = (const float4*)d_in[0];
    const float4* K = (const float4*)d_in[1];
    const float4* V = (const float4*)d_in[2];
    float4* O = (float4*)d_out;

    const int total_warps = Bq * Lq * (Hq / 2);      // 32768
    const int threads = 256;
    const int blocks = (total_warps * 32) / threads; // 4096
    logsparse_attn_kernel<<<blocks, threads>>>(Q, K, V, O);
}

// round 11
// speedup vs baseline: 1.1875x; 1.1875x over previous
#include <cuda_runtime.h>
#include <math.h>

#define Bq 4
#define Lq 2048
#define Hq 8
#define Dq 64
#define NSLOT 12                 // self + offsets 2^0 .. 2^10
#define SLAB4 (Hq * Dq / 4)      // 128 x 16B chunks per (b,l) slab

// exp(score) = ex2(dot * 0.125 * log2(e))
#define EXC 0.18033688011112042f

__device__ __forceinline__ float ex2f(float x) {
    float r;
    asm("ex2.approx.f32 %0, %1;" : "=f"(r) : "f"(x));
    return r;
}

// One warp per (b, l, head-pair); lane ln owns 16B chunk ln of the 512B
// contiguous head-pair slab (lanes 0-15 even head, 16-31 odd head).
template <bool FULL>
__device__ __forceinline__ void run_query(
    const float4* __restrict__ Q4, const float4* __restrict__ K4,
    const float4* __restrict__ V4, float4* __restrict__ O4,
    int base, int l, int hl)     // hl = lane & 15 (index within half)
{
    const float4 q = Q4[base];

    // ---- phase 1: 12 front-batched K loads, per-lane partial dots ----
    float v[16];
#pragma unroll
    for (int t = 0; t < NSLOT; t++) {
        const int off = (t == 0) ? 0 : (1 << (t - 1));
        const bool ok = FULL || (off <= l);
        const int kb = base - (ok ? off * SLAB4 : 0);  // imm offset in FULL path
        const float4 k = K4[kb];
        v[t] = q.x*k.x + q.y*k.y + q.z*k.z + q.w*k.w;
    }
#pragma unroll
    for (int t = NSLOT; t < 16; t++) v[t] = 0.0f;

    // ---- multi-value butterfly: 15 shfls reduce ALL 16 slots; after this,
    //      lane hl (in each 16-lane half) holds the full dot of slot hl ----
#pragma unroll
    for (int m = 8; m >= 1; m >>= 1) {
#pragma unroll
        for (int j = 0; j < m; j++) {
            const float send = (hl & m) ? v[j] : v[j + m];
            const float other = __shfl_xor_sync(0xffffffffu, send, m);
            v[j] = ((hl & m) ? v[j + m] : v[j]) + other;
        }
    }

    // per-lane validity of slot hl
    bool okl;
    if (FULL) okl = (hl < NSLOT);
    else      okl = (hl == 0) || ((hl < NSLOT) && ((1 << (hl - 1)) <= l));

    // one exp for all 12 slots; scale+log2e folded into one multiply
    const float e = okl ? ex2f(v[0] * EXC) : 0.0f;

    // 16-lane butterfly sum of e -> denominator in every lane
    float sum = e;
    sum += __shfl_xor_sync(0xffffffffu, sum, 1);
    sum += __shfl_xor_sync(0xffffffffu, sum, 2);
    sum += __shfl_xor_sync(0xffffffffu, sum, 4);
    sum += __shfl_xor_sync(0xffffffffu, sum, 8);
    const float inv = 1.0f / sum;

    // ---- phase 2: V gathers + width-16 prob broadcast + accumulate ----
    float4 acc = {0.f, 0.f, 0.f, 0.f};
#pragma unroll
    for (int t = 0; t < NSLOT; t++) {
        const int off = (t == 0) ? 0 : (1 << (t - 1));
        const bool ok = FULL || (off <= l);
        const int vb = base - (ok ? off * SLAB4 : 0);
        const float4 vv = V4[vb];
        const float p = __shfl_sync(0xffffffffu, e, t, 16);  // 0 if slot invalid
        acc.x += p * vv.x;
        acc.y += p * vv.y;
        acc.z += p * vv.z;
        acc.w += p * vv.w;
    }
    acc.x *= inv; acc.y *= inv; acc.z *= inv; acc.w *= inv;
    O4[base] = acc;
}

__global__ __launch_bounds__(128) void logsparse_attn_kernel(
    const float4* __restrict__ Q4,
    const float4* __restrict__ K4,
    const float4* __restrict__ V4,
    float4* __restrict__ O4)
{
    const int wid  = (blockIdx.x * blockDim.x + threadIdx.x) >> 5;
    const int lane = threadIdx.x & 31;
    const int g = wid & (Hq / 2 - 1);            // head-pair 0..3
    const int s = wid >> 2;                      // b*L + l
    const int l = s & (Lq - 1);

    const int base = s * SLAB4 + g * 32 + lane;  // 16B-chunk index
    const int hl = lane & 15;

    if (l >= 1024) {
        run_query<true>(Q4, K4, V4, O4, base, l, hl);
    } else {
        run_query<false>(Q4, K4, V4, O4, base, l, hl);
    }
}

extern "C" void kernel_launch(void* const* d_in, const int* in_sizes, int n_in,
                              void* d_out, int out_size)
{
    const float4* Q = (const float4*)d_in[0];
    const float4* K = (const float4*)d_in[1];
    const float4* V = (const float4*)d_in[2];
    float4* O = (float4*)d_out;

    const int total_warps = Bq * Lq * (Hq / 2);      // 32768
    const int threads = 128;                          // 4 warps/CTA: finer occupancy quantization
    const int blocks = (total_warps * 32) / threads;  // 8192
    logsparse_attn_kernel<<<blocks, threads>>>(Q, K, V, O);
}